// round 4
// baseline (speedup 1.0000x reference)
#include <cuda_runtime.h>

#define N_NODES 100000
#define N_EDGES 100000
#define N_PINS  1600000
#define IN_DIM  32
#define HID     64
#define NEG     0.01f

// ---------------- scratch: __device__ globals, referenced DIRECTLY ----------
__device__ __align__(16) float g_A  [N_NODES * HID];   // x @ W
__device__ __align__(16) float g_HE [N_EDGES * HID];   // per-edge accumulator
__device__ __align__(16) float g_OUT[N_NODES * HID];   // per-node accumulator
__device__ __align__(16) float g_H  [N_NODES * HID];   // activated hidden state
__device__ __align__(16) float g_MU [N_NODES * HID];   // mu
__device__ __align__(16) float g_Dinv[N_NODES];
__device__ __align__(16) float g_Binv[N_EDGES];
__device__ __align__(16) float g_dvec[N_NODES];
__device__ float g_sumsq;

// ---------------- utility kernels ------------------------------------------
__global__ void zero_deg_kernel() {
    int i = blockIdx.x * blockDim.x + threadIdx.x;
    int stride = gridDim.x * blockDim.x;
    float4 z = make_float4(0.f, 0.f, 0.f, 0.f);
    for (int t = i; t < N_NODES / 4; t += stride) ((float4*)g_Dinv)[t] = z;
    for (int t = i; t < N_EDGES / 4; t += stride) ((float4*)g_Binv)[t] = z;
    if (i == 0) g_sumsq = 0.f;
}

__global__ void zero_acc_kernel() {
    int i = blockIdx.x * blockDim.x + threadIdx.x;
    int stride = gridDim.x * blockDim.x;
    float4 z = make_float4(0.f, 0.f, 0.f, 0.f);
    for (int t = i; t < N_EDGES * 16; t += stride) ((float4*)g_HE)[t] = z;
    for (int t = i; t < N_NODES * 16; t += stride) ((float4*)g_OUT)[t] = z;
}

__global__ void deg_kernel(const int* __restrict__ nidx,
                           const int* __restrict__ eidx) {
    int i = blockIdx.x * blockDim.x + threadIdx.x;
    if (i < N_PINS) {
        atomicAdd(&g_Dinv[nidx[i]], 1.0f);
        atomicAdd(&g_Binv[eidx[i]], 1.0f);
    }
}

__global__ void inv2_kernel() {
    int i = blockIdx.x * blockDim.x + threadIdx.x;
    if (i < N_NODES) {
        float va = g_Dinv[i]; g_Dinv[i] = va > 0.f ? 1.0f / va : 0.0f;
        float vb = g_Binv[i]; g_Binv[i] = vb > 0.f ? 1.0f / vb : 0.0f;
    }
}

// ---------------- dense matmul: g_A[N,64] = X[N,K] @ W[K,64] ----------------
// XSEL: 0 -> X param (harness input), 1 -> g_H
template <int XSEL, int K>
__global__ void matmul64_kernel(const float* __restrict__ Xp,
                                const float* __restrict__ W) {
    const float* X = (XSEL == 0) ? Xp : g_H;
    __shared__ float Ws[K * 64];
    __shared__ float Xs[16][K];
    int tid = threadIdx.x;  // 256
    for (int i = tid; i < K * 64; i += 256) Ws[i] = W[i];
    int node0 = blockIdx.x * 16;
    for (int i = tid; i < 16 * K; i += 256) {
        int r = i / K, c = i % K;
        int n = node0 + r;
        Xs[r][c] = (n < N_NODES) ? X[(long)n * K + c] : 0.f;
    }
    __syncthreads();
    int j = tid & 63;
    int rbase = tid >> 6;  // 0..3
    #pragma unroll
    for (int it = 0; it < 4; it++) {
        int r = rbase + it * 4;
        int n = node0 + r;
        if (n < N_NODES) {
            float acc = 0.f;
            #pragma unroll
            for (int k = 0; k < K; k++) acc += Xs[r][k] * Ws[k * 64 + j];
            g_A[(long)n * 64 + j] = acc;
        }
    }
}

// ---------------- scatter passes ---------------------------------------------
// MODE 0: g_HE[eidx[p]] += g_A[nidx[p]]               (node -> edge)
// MODE 1: g_OUT[nidx[p]] += g_HE[eidx[p]] * Binv[e]   (edge -> node)
// 16 threads per pin, each owns 4 contiguous floats.
template <int MODE>
__global__ void scatter64_kernel(const int* __restrict__ nidx,
                                 const int* __restrict__ eidx) {
    long t = (long)blockIdx.x * blockDim.x + threadIdx.x;
    int pin = (int)(t >> 4);
    if (pin >= N_PINS) return;
    int q = (int)(t & 15) << 2;
    int n = nidx[pin];
    int e = eidx[pin];
    if (MODE == 0) {
        float4 v = *(const float4*)(g_A + (long)n * 64 + q);
        float* p = g_HE + (long)e * 64 + q;
        atomicAdd(p + 0, v.x);
        atomicAdd(p + 1, v.y);
        atomicAdd(p + 2, v.z);
        atomicAdd(p + 3, v.w);
    } else {
        float4 v = *(const float4*)(g_HE + (long)e * 64 + q);
        float sc = g_Binv[e];
        float* p = g_OUT + (long)n * 64 + q;
        atomicAdd(p + 0, v.x * sc);
        atomicAdd(p + 1, v.y * sc);
        atomicAdd(p + 2, v.z * sc);
        atomicAdd(p + 3, v.w * sc);
    }
}

// ---------------- finalize variants -----------------------------------------
__device__ __forceinline__ float leaky(float v) { return v >= 0.f ? v : NEG * v; }

// g_H = leaky(layernorm(g_OUT*Dinv + b; g, be))   (one warp per node)
__global__ void finalize_ln_kernel(const float* __restrict__ b,
                                   const float* __restrict__ g,
                                   const float* __restrict__ be) {
    int w = threadIdx.x >> 5;
    int lane = threadIdx.x & 31;
    int n = blockIdx.x * 8 + w;
    if (n >= N_NODES) return;
    float di = g_Dinv[n];
    float v0 = g_OUT[(long)n * 64 + lane]      * di + b[lane];
    float v1 = g_OUT[(long)n * 64 + lane + 32] * di + b[lane + 32];
    float s = v0 + v1;
    float sq = v0 * v0 + v1 * v1;
    #pragma unroll
    for (int o = 16; o > 0; o >>= 1) {
        s  += __shfl_xor_sync(0xffffffff, s,  o);
        sq += __shfl_xor_sync(0xffffffff, sq, o);
    }
    float mean = s * (1.0f / 64.0f);
    float var  = sq * (1.0f / 64.0f) - mean * mean;
    float rstd = rsqrtf(var + 1e-5f);
    float y0 = (v0 - mean) * rstd * g[lane]      + be[lane];
    float y1 = (v1 - mean) * rstd * g[lane + 32] + be[lane + 32];
    g_H[(long)n * 64 + lane]      = leaky(y0);
    g_H[(long)n * 64 + lane + 32] = leaky(y1);
}

// out = f(g_OUT*Dinv + b).  OSEL: 0 -> g_H, 1 -> g_MU, 2 -> param pointer
template <int OSEL, int LEAKYF>
__global__ void finalize_elem_kernel(const float* __restrict__ b,
                                     float* __restrict__ outp) {
    int t = blockIdx.x * blockDim.x + threadIdx.x;  // 2 floats per thread
    if (t >= N_NODES * 32) return;
    int n = t >> 5;
    int q = (t & 31) << 1;
    float di = g_Dinv[n];
    float a0 = g_OUT[(long)n * 64 + q]     * di + b[q];
    float a1 = g_OUT[(long)n * 64 + q + 1] * di + b[q + 1];
    if (LEAKYF) { a0 = leaky(a0); a1 = leaky(a1); }
    float* out = (OSEL == 0) ? g_H : (OSEL == 1) ? g_MU : outp;
    out[(long)n * 64 + q]     = a0;
    out[(long)n * 64 + q + 1] = a1;
}

// ---------------- decoder: 64 -> 32 -> 8 -> 1 + sumsq -----------------------
__global__ void decode_kernel(const float* __restrict__ dW1, const float* __restrict__ db1,
                              const float* __restrict__ dW2, const float* __restrict__ db2,
                              const float* __restrict__ dW3, const float* __restrict__ db3) {
    __shared__ float W1s[64 * 32];
    __shared__ float W2s[32 * 8];
    __shared__ float W3s[8];
    __shared__ float b1s[32], b2s[8], b3s;
    __shared__ float mus[4][64];
    __shared__ float v1s[4][32];
    __shared__ float v2s[4][8];
    __shared__ float dsq[4];
    int tid = threadIdx.x;  // 128
    for (int i = tid; i < 2048; i += 128) W1s[i] = dW1[i];
    for (int i = tid; i < 256;  i += 128) W2s[i] = dW2[i];
    if (tid < 8)  W3s[tid] = dW3[tid];
    if (tid < 32) b1s[tid] = db1[tid];
    if (tid >= 32 && tid < 40) b2s[tid - 32] = db2[tid - 32];
    if (tid == 40) b3s = db3[0];
    int w = tid >> 5, lane = tid & 31;
    int node = blockIdx.x * 4 + w;
    bool active = node < N_NODES;
    if (active) {
        mus[w][lane]      = g_MU[(long)node * 64 + lane];
        mus[w][lane + 32] = g_MU[(long)node * 64 + lane + 32];
    }
    __syncthreads();
    float d = 0.f;
    if (active) {
        float a1 = b1s[lane];
        #pragma unroll
        for (int k = 0; k < 64; k++) a1 += mus[w][k] * W1s[k * 32 + lane];
        v1s[w][lane] = leaky(a1);
        __syncwarp();
        if (lane < 8) {
            float a2 = b2s[lane];
            #pragma unroll
            for (int k = 0; k < 32; k++) a2 += v1s[w][k] * W2s[k * 8 + lane];
            v2s[w][lane] = leaky(a2);
        }
        __syncwarp();
        if (lane == 0) {
            d = b3s;
            #pragma unroll
            for (int o = 0; o < 8; o++) d += v2s[w][o] * W3s[o];
            g_dvec[node] = d;
        }
    }
    if (lane == 0) dsq[w] = active ? d * d : 0.f;
    __syncthreads();
    if (tid == 0) atomicAdd(&g_sumsq, dsq[0] + dsq[1] + dsq[2] + dsq[3]);
}

__global__ void norm_write_kernel(float* __restrict__ oz, float* __restrict__ om) {
    int i = blockIdx.x * blockDim.x + threadIdx.x;
    if (i >= N_NODES) return;
    float nrm = sqrtf(g_sumsq);
    float sc = 1.0f / fmaxf(nrm, 1e-8f);
    float v = g_dvec[i] * sc;
    oz[i] = v;
    om[i] = v;
}

// ---------------- host launch ------------------------------------------------
extern "C" void kernel_launch(void* const* d_in, const int* in_sizes, int n_in,
                              void* d_out, int out_size) {
    const float* x   = (const float*)d_in[0];
    const int*   hei = (const int*)d_in[1];   // int32! (JAX x64 disabled)
    const float *W1 = (const float*)d_in[2],  *b1  = (const float*)d_in[3];
    const float *g1 = (const float*)d_in[4],  *be1 = (const float*)d_in[5];
    const float *W2 = (const float*)d_in[6],  *b2  = (const float*)d_in[7];
    const float *Wmu= (const float*)d_in[8],  *bmu = (const float*)d_in[9];
    const float *Wlv= (const float*)d_in[10], *blv = (const float*)d_in[11];
    const float *dW1= (const float*)d_in[12], *db1 = (const float*)d_in[13];
    const float *dW2= (const float*)d_in[14], *db2 = (const float*)d_in[15];
    const float *dW3= (const float*)d_in[16], *db3 = (const float*)d_in[17];

    const int* nidx = hei;
    const int* eidx = hei + N_PINS;

    float* out   = (float*)d_out;
    float* out_z = out;
    float* out_m = out + N_NODES;
    float* out_lv= out + 2 * N_NODES;

    const int TB = 256;
    const int pins_blocks    = (N_PINS + TB - 1) / TB;
    const int scatter_blocks = (N_PINS * 16) / TB;         // exact multiple
    const int elem_blocks    = (N_NODES * 32 + TB - 1) / TB;
    const int mm_blocks      = (N_NODES + 15) / 16;
    const int ln_blocks      = (N_NODES + 7) / 8;
    const int dec_blocks     = (N_NODES + 3) / 4;
    const int n_blocks       = (N_NODES + TB - 1) / TB;
    const int zero_blocks    = 2048;

    // degrees
    zero_deg_kernel<<<zero_blocks, TB>>>();
    deg_kernel<<<pins_blocks, TB>>>(nidx, eidx);
    inv2_kernel<<<n_blocks, TB>>>();

    // hconv1 + layernorm + leaky -> g_H
    matmul64_kernel<0, IN_DIM><<<mm_blocks, TB>>>(x, W1);
    zero_acc_kernel<<<zero_blocks, TB>>>();
    scatter64_kernel<0><<<scatter_blocks, TB>>>(nidx, eidx);
    scatter64_kernel<1><<<scatter_blocks, TB>>>(nidx, eidx);
    finalize_ln_kernel<<<ln_blocks, TB>>>(b1, g1, be1);

    // hconv2 + leaky -> g_H
    matmul64_kernel<1, HID><<<mm_blocks, TB>>>(nullptr, W2);
    zero_acc_kernel<<<zero_blocks, TB>>>();
    scatter64_kernel<0><<<scatter_blocks, TB>>>(nidx, eidx);
    scatter64_kernel<1><<<scatter_blocks, TB>>>(nidx, eidx);
    finalize_elem_kernel<0, 1><<<elem_blocks, TB>>>(b2, nullptr);

    // mu -> g_MU
    matmul64_kernel<1, HID><<<mm_blocks, TB>>>(nullptr, Wmu);
    zero_acc_kernel<<<zero_blocks, TB>>>();
    scatter64_kernel<0><<<scatter_blocks, TB>>>(nidx, eidx);
    scatter64_kernel<1><<<scatter_blocks, TB>>>(nidx, eidx);
    finalize_elem_kernel<1, 0><<<elem_blocks, TB>>>(bmu, nullptr);

    // logvar -> d_out section
    matmul64_kernel<1, HID><<<mm_blocks, TB>>>(nullptr, Wlv);
    zero_acc_kernel<<<zero_blocks, TB>>>();
    scatter64_kernel<0><<<scatter_blocks, TB>>>(nidx, eidx);
    scatter64_kernel<1><<<scatter_blocks, TB>>>(nidx, eidx);
    finalize_elem_kernel<2, 0><<<elem_blocks, TB>>>(blv, out_lv);

    // decode(z=mu) once; z_orth == mu_orth in eval mode
    decode_kernel<<<dec_blocks, 128>>>(dW1, db1, dW2, db2, dW3, db3);
    norm_write_kernel<<<n_blocks, TB>>>(out_z, out_m);
}

// round 5
// speedup vs baseline: 3.8198x; 3.8198x over previous
#include <cuda_runtime.h>

#define N_NODES 100000
#define N_EDGES 100000
#define N_PINS  1600000
#define IN_DIM  32
#define HID     64
#define NEG     0.01f
#define NB      391           // ceil(100000/256)

__device__ __forceinline__ float leaky(float v) { return v >= 0.f ? v : NEG * v; }

// ---------------- scratch: __device__ globals, referenced only in-kernel ----
__device__ __align__(16) float g_HE [N_EDGES * HID];   // edge-gather result
__device__ __align__(16) float g_G  [N_NODES * HID];   // node-gather result
__device__ __align__(16) float g_A  [N_NODES * HID];   // matmul out pre-LN
__device__ __align__(16) float g_H  [N_NODES * HID];   // hidden state
__device__ __align__(16) float g_MU [N_NODES * HID];   // mu
__device__ __align__(16) float g_dvec[N_NODES];
__device__ float g_sumsq;

// CSR
__device__ int g_ecnt [N_EDGES];
__device__ int g_ncnt [N_NODES];
__device__ int g_estart[N_EDGES + 1];
__device__ int g_nstart[N_NODES + 1];
__device__ int g_epins[N_PINS];   // node ids grouped by edge
__device__ int g_npins[N_PINS];   // edge ids grouped by node
__device__ int g_bsum_e[NB];
__device__ int g_bsum_n[NB];

// ---------------- CSR build --------------------------------------------------
__global__ void zero_cnt_kernel() {
    int i = blockIdx.x * blockDim.x + threadIdx.x;
    if (i < N_EDGES) g_ecnt[i] = 0;
    if (i < N_NODES) g_ncnt[i] = 0;
    if (i == 0) g_sumsq = 0.f;
}

__global__ void hist_kernel(const int* __restrict__ nidx, const int* __restrict__ eidx) {
    int i = blockIdx.x * blockDim.x + threadIdx.x;
    if (i < N_PINS) {
        atomicAdd(&g_ncnt[nidx[i]], 1);
        atomicAdd(&g_ecnt[eidx[i]], 1);
    }
}

// per-block sums of counts
__global__ void scan1_kernel() {
    __shared__ int se[256], sn[256];
    int tid = threadIdx.x;
    int gid = blockIdx.x * 256 + tid;
    se[tid] = (gid < N_EDGES) ? g_ecnt[gid] : 0;
    sn[tid] = (gid < N_NODES) ? g_ncnt[gid] : 0;
    __syncthreads();
    for (int off = 128; off > 0; off >>= 1) {
        if (tid < off) { se[tid] += se[tid + off]; sn[tid] += sn[tid + off]; }
        __syncthreads();
    }
    if (tid == 0) { g_bsum_e[blockIdx.x] = se[0]; g_bsum_n[blockIdx.x] = sn[0]; }
}

// exclusive scan of block sums (single block, Hillis-Steele over 512)
__global__ void scan2_kernel() {
    __shared__ int se[512], sn[512];
    int tid = threadIdx.x;
    int ve = (tid < NB) ? g_bsum_e[tid] : 0;
    int vn = (tid < NB) ? g_bsum_n[tid] : 0;
    se[tid] = ve; sn[tid] = vn;
    __syncthreads();
    for (int off = 1; off < 512; off <<= 1) {
        int ae = (tid >= off) ? se[tid - off] : 0;
        int an = (tid >= off) ? sn[tid - off] : 0;
        __syncthreads();
        se[tid] += ae; sn[tid] += an;
        __syncthreads();
    }
    if (tid < NB) { g_bsum_e[tid] = se[tid] - ve; g_bsum_n[tid] = sn[tid] - vn; }
    if (tid == 0) { g_estart[N_EDGES] = N_PINS; g_nstart[N_NODES] = N_PINS; }
}

// per-block exclusive scan + offset -> starts; zero counts for reuse as cursors
__global__ void scan3_kernel() {
    __shared__ int se[256], sn[256];
    int tid = threadIdx.x;
    int gid = blockIdx.x * 256 + tid;
    int ve = (gid < N_EDGES) ? g_ecnt[gid] : 0;
    int vn = (gid < N_NODES) ? g_ncnt[gid] : 0;
    se[tid] = ve; sn[tid] = vn;
    __syncthreads();
    for (int off = 1; off < 256; off <<= 1) {
        int ae = (tid >= off) ? se[tid - off] : 0;
        int an = (tid >= off) ? sn[tid - off] : 0;
        __syncthreads();
        se[tid] += ae; sn[tid] += an;
        __syncthreads();
    }
    if (gid < N_EDGES) { g_estart[gid] = g_bsum_e[blockIdx.x] + se[tid] - ve; g_ecnt[gid] = 0; }
    if (gid < N_NODES) { g_nstart[gid] = g_bsum_n[blockIdx.x] + sn[tid] - vn; g_ncnt[gid] = 0; }
}

__global__ void fill_kernel(const int* __restrict__ nidx, const int* __restrict__ eidx) {
    int i = blockIdx.x * blockDim.x + threadIdx.x;
    if (i >= N_PINS) return;
    int n = nidx[i], e = eidx[i];
    int pe = g_estart[e] + atomicAdd(&g_ecnt[e], 1);
    g_epins[pe] = n;
    int pn = g_nstart[n] + atomicAdd(&g_ncnt[n], 1);
    g_npins[pn] = e;
}

// ---------------- gather: dst[row] = (1/deg) * sum_{p in row} src[pin_p] ----
// One warp per row. W = 32 or 64 columns.
// SIDE 0: edge side (estart/epins, dst=g_HE). SIDE 1: node side (nstart/npins, dst=g_G).
// SRCSEL 0: param Xp. 1: g_HE. 2: g_H.
template <int W, int SIDE, int SRCSEL>
__global__ void gather_kernel(const float* __restrict__ Xp) {
    int row  = (blockIdx.x * blockDim.x + threadIdx.x) >> 5;
    int lane = threadIdx.x & 31;
    if (row >= N_NODES) return;   // N_NODES == N_EDGES
    const int* start = (SIDE == 0) ? g_estart : g_nstart;
    const int* pins  = (SIDE == 0) ? g_epins  : g_npins;
    const float* src = (SRCSEL == 0) ? Xp : (SRCSEL == 1) ? g_HE : g_H;
    float* dst = (SIDE == 0) ? g_HE : g_G;
    int s = start[row], e = start[row + 1];
    float inv = (e > s) ? 1.0f / (float)(e - s) : 0.0f;
    float a0 = 0.f, a1 = 0.f;
    for (int i = s; i < e; i += 32) {
        int cnt = e - i; if (cnt > 32) cnt = 32;
        int pid = (lane < cnt) ? pins[i + lane] : 0;
        #pragma unroll 4
        for (int j = 0; j < cnt; j++) {
            int p = __shfl_sync(0xffffffff, pid, j);
            a0 += src[(long)p * W + lane];
            if (W == 64) a1 += src[(long)p * W + lane + 32];
        }
    }
    dst[(long)row * W + lane] = a0 * inv;
    if (W == 64) dst[(long)row * W + lane + 32] = a1 * inv;
}

// ---------------- matmul: out[N,64] = g_G[N,K] @ W[K,64] + bias (opt leaky) -
// 256 threads, 32 rows x 64 cols per block; thread computes 2 rows x 4 cols.
// DST 0: g_A, 1: g_H, 2: g_MU, 3: outp param.
template <int K, int DST, int ACT>
__global__ void matmul_kernel(const float* __restrict__ W,
                              const float* __restrict__ bias,
                              float* __restrict__ outp) {
    __shared__ __align__(16) float Ws[K * 64];
    __shared__ float Xs[32][K + 1];
    int tid = threadIdx.x;
    for (int i = tid; i < K * 64; i += 256) Ws[i] = W[i];
    int node0 = blockIdx.x * 32;   // 100000 % 32 handled: 3125*32 == 100000
    for (int i = tid; i < 32 * K; i += 256) {
        int r = i / K, c = i % K;
        Xs[r][c] = g_G[(long)(node0 + r) * K + c];
    }
    __syncthreads();
    int j0 = (tid & 15) << 2;
    int r0 = (tid >> 4) << 1;
    float acc[2][4] = {};
    #pragma unroll
    for (int k = 0; k < K; k++) {
        float x0 = Xs[r0][k], x1 = Xs[r0 + 1][k];
        float4 w = *(const float4*)&Ws[k * 64 + j0];
        acc[0][0] += x0 * w.x; acc[0][1] += x0 * w.y; acc[0][2] += x0 * w.z; acc[0][3] += x0 * w.w;
        acc[1][0] += x1 * w.x; acc[1][1] += x1 * w.y; acc[1][2] += x1 * w.z; acc[1][3] += x1 * w.w;
    }
    float* out = (DST == 0) ? g_A : (DST == 1) ? g_H : (DST == 2) ? g_MU : outp;
    float b0 = bias[j0], b1 = bias[j0 + 1], b2 = bias[j0 + 2], b3 = bias[j0 + 3];
    #pragma unroll
    for (int rr = 0; rr < 2; rr++) {
        float4 v;
        v.x = acc[rr][0] + b0; v.y = acc[rr][1] + b1;
        v.z = acc[rr][2] + b2; v.w = acc[rr][3] + b3;
        if (ACT) { v.x = leaky(v.x); v.y = leaky(v.y); v.z = leaky(v.z); v.w = leaky(v.w); }
        *(float4*)&out[(long)(node0 + r0 + rr) * 64 + j0] = v;
    }
}

// ---------------- layernorm + leaky: g_H = leaky(LN(g_A; g, be)) ------------
__global__ void finalize_ln_kernel(const float* __restrict__ g,
                                   const float* __restrict__ be) {
    int w = threadIdx.x >> 5;
    int lane = threadIdx.x & 31;
    int n = blockIdx.x * 8 + w;
    if (n >= N_NODES) return;
    float v0 = g_A[(long)n * 64 + lane];
    float v1 = g_A[(long)n * 64 + lane + 32];
    float s = v0 + v1, sq = v0 * v0 + v1 * v1;
    #pragma unroll
    for (int o = 16; o > 0; o >>= 1) {
        s  += __shfl_xor_sync(0xffffffff, s,  o);
        sq += __shfl_xor_sync(0xffffffff, sq, o);
    }
    float mean = s * (1.0f / 64.0f);
    float var  = sq * (1.0f / 64.0f) - mean * mean;
    float rstd = rsqrtf(var + 1e-5f);
    float y0 = (v0 - mean) * rstd * g[lane]      + be[lane];
    float y1 = (v1 - mean) * rstd * g[lane + 32] + be[lane + 32];
    g_H[(long)n * 64 + lane]      = leaky(y0);
    g_H[(long)n * 64 + lane + 32] = leaky(y1);
}

// ---------------- decoder: 64 -> 32 -> 8 -> 1 + sumsq -----------------------
__global__ void decode_kernel(const float* __restrict__ dW1, const float* __restrict__ db1,
                              const float* __restrict__ dW2, const float* __restrict__ db2,
                              const float* __restrict__ dW3, const float* __restrict__ db3) {
    __shared__ float W1s[64 * 32];
    __shared__ float W2s[32 * 8];
    __shared__ float W3s[8];
    __shared__ float b1s[32], b2s[8], b3s;
    __shared__ float mus[4][64];
    __shared__ float v1s[4][32];
    __shared__ float v2s[4][8];
    __shared__ float dsq[4];
    int tid = threadIdx.x;  // 128
    for (int i = tid; i < 2048; i += 128) W1s[i] = dW1[i];
    for (int i = tid; i < 256;  i += 128) W2s[i] = dW2[i];
    if (tid < 8)  W3s[tid] = dW3[tid];
    if (tid < 32) b1s[tid] = db1[tid];
    if (tid >= 32 && tid < 40) b2s[tid - 32] = db2[tid - 32];
    if (tid == 40) b3s = db3[0];
    int w = tid >> 5, lane = tid & 31;
    int node = blockIdx.x * 4 + w;
    bool active = node < N_NODES;
    if (active) {
        mus[w][lane]      = g_MU[(long)node * 64 + lane];
        mus[w][lane + 32] = g_MU[(long)node * 64 + lane + 32];
    }
    __syncthreads();
    float d = 0.f;
    if (active) {
        float a1 = b1s[lane];
        #pragma unroll
        for (int k = 0; k < 64; k++) a1 += mus[w][k] * W1s[k * 32 + lane];
        v1s[w][lane] = leaky(a1);
        __syncwarp();
        if (lane < 8) {
            float a2 = b2s[lane];
            #pragma unroll
            for (int k = 0; k < 32; k++) a2 += v1s[w][k] * W2s[k * 8 + lane];
            v2s[w][lane] = leaky(a2);
        }
        __syncwarp();
        if (lane == 0) {
            d = b3s;
            #pragma unroll
            for (int o = 0; o < 8; o++) d += v2s[w][o] * W3s[o];
            g_dvec[node] = d;
        }
    }
    if (lane == 0) dsq[w] = active ? d * d : 0.f;
    __syncthreads();
    if (tid == 0) atomicAdd(&g_sumsq, dsq[0] + dsq[1] + dsq[2] + dsq[3]);
}

__global__ void norm_write_kernel(float* __restrict__ oz, float* __restrict__ om) {
    int i = blockIdx.x * blockDim.x + threadIdx.x;
    if (i >= N_NODES) return;
    float sc = 1.0f / fmaxf(sqrtf(g_sumsq), 1e-8f);
    float v = g_dvec[i] * sc;
    oz[i] = v;
    om[i] = v;
}

// ---------------- host launch ------------------------------------------------
extern "C" void kernel_launch(void* const* d_in, const int* in_sizes, int n_in,
                              void* d_out, int out_size) {
    const float* x   = (const float*)d_in[0];
    const int*   hei = (const int*)d_in[1];   // int32 (JAX x64 disabled)
    const float *W1 = (const float*)d_in[2],  *b1  = (const float*)d_in[3];
    const float *g1 = (const float*)d_in[4],  *be1 = (const float*)d_in[5];
    const float *W2 = (const float*)d_in[6],  *b2  = (const float*)d_in[7];
    const float *Wmu= (const float*)d_in[8],  *bmu = (const float*)d_in[9];
    const float *Wlv= (const float*)d_in[10], *blv = (const float*)d_in[11];
    const float *dW1= (const float*)d_in[12], *db1 = (const float*)d_in[13];
    const float *dW2= (const float*)d_in[14], *db2 = (const float*)d_in[15];
    const float *dW3= (const float*)d_in[16], *db3 = (const float*)d_in[17];

    const int* nidx = hei;
    const int* eidx = hei + N_PINS;

    float* out    = (float*)d_out;
    float* out_z  = out;
    float* out_m  = out + N_NODES;
    float* out_lv = out + 2 * N_NODES;

    const int TB = 256;
    const int pins_blocks   = (N_PINS + TB - 1) / TB;      // 6250
    const int gather_blocks = (N_NODES * 32) / TB;         // 12500 (warp/row)
    const int mm_blocks     = N_NODES / 32;                // 3125
    const int ln_blocks     = (N_NODES + 7) / 8;
    const int dec_blocks    = (N_NODES + 3) / 4;
    const int n_blocks      = (N_NODES + TB - 1) / TB;

    // CSR build
    zero_cnt_kernel<<<NB, TB>>>();
    hist_kernel<<<pins_blocks, TB>>>(nidx, eidx);
    scan1_kernel<<<NB, TB>>>();
    scan2_kernel<<<1, 512>>>();
    scan3_kernel<<<NB, TB>>>();
    fill_kernel<<<pins_blocks, TB>>>(nidx, eidx);

    // layer 1: gather(x) @ W1 + b1 -> LN -> leaky -> g_H   (32-wide gathers)
    gather_kernel<32, 0, 0><<<gather_blocks, TB>>>(x);
    gather_kernel<32, 1, 1><<<gather_blocks, TB>>>(nullptr);
    matmul_kernel<32, 0, 0><<<mm_blocks, TB>>>(W1, b1, nullptr);
    finalize_ln_kernel<<<ln_blocks, TB>>>(g1, be1);

    // layer 2: gather(g_H) @ W2 + b2 -> leaky -> g_H
    gather_kernel<64, 0, 2><<<gather_blocks, TB>>>(nullptr);
    gather_kernel<64, 1, 1><<<gather_blocks, TB>>>(nullptr);
    matmul_kernel<64, 1, 1><<<mm_blocks, TB>>>(W2, b2, nullptr);

    // mu / logvar share one gathered tensor: gather(g_H) once
    gather_kernel<64, 0, 2><<<gather_blocks, TB>>>(nullptr);
    gather_kernel<64, 1, 1><<<gather_blocks, TB>>>(nullptr);
    matmul_kernel<64, 2, 0><<<mm_blocks, TB>>>(Wmu, bmu, nullptr);
    matmul_kernel<64, 3, 0><<<mm_blocks, TB>>>(Wlv, blv, out_lv);

    // decode(z = mu) once; z_orth == mu_orth in eval mode
    decode_kernel<<<dec_blocks, 128>>>(dW1, db1, dW2, db2, dW3, db3);
    norm_write_kernel<<<n_blocks, TB>>>(out_z, out_m);
}

// round 6
// speedup vs baseline: 4.4180x; 1.1566x over previous
#include <cuda_runtime.h>

#define N_NODES 100000
#define N_EDGES 100000
#define N_PINS  1600000
#define IN_DIM  32
#define HID     64
#define NEG     0.01f
#define NB      391           // ceil(100000/256)

__device__ __forceinline__ float leaky(float v) { return v >= 0.f ? v : NEG * v; }

// ---------------- scratch: __device__ globals, referenced only in-kernel ----
__device__ __align__(16) float g_HE [N_EDGES * HID];   // edge-gather result
__device__ __align__(16) float g_G  [N_NODES * HID];   // node-gather result
__device__ __align__(16) float g_H  [N_NODES * HID];   // hidden state
__device__ __align__(16) float g_MU [N_NODES * HID];   // mu
__device__ __align__(16) float g_dvec[N_NODES];
__device__ float g_sumsq;

// CSR
__device__ int g_ecnt [N_EDGES];
__device__ int g_ncnt [N_NODES];
__device__ int g_estart[N_EDGES + 1];
__device__ int g_nstart[N_NODES + 1];
__device__ int g_epins[N_PINS];   // node ids grouped by edge
__device__ int g_npins[N_PINS];   // edge ids grouped by node
__device__ int g_bsum_e[NB];
__device__ int g_bsum_n[NB];

// ---------------- CSR build --------------------------------------------------
__global__ void zero_cnt_kernel() {
    int i = blockIdx.x * blockDim.x + threadIdx.x;
    if (i < N_EDGES) g_ecnt[i] = 0;
    if (i < N_NODES) g_ncnt[i] = 0;
    if (i == 0) g_sumsq = 0.f;
}

__global__ void hist_kernel(const int* __restrict__ nidx, const int* __restrict__ eidx) {
    int i = blockIdx.x * blockDim.x + threadIdx.x;
    if (i < N_PINS) {
        atomicAdd(&g_ncnt[nidx[i]], 1);
        atomicAdd(&g_ecnt[eidx[i]], 1);
    }
}

__global__ void scan1_kernel() {
    __shared__ int se[256], sn[256];
    int tid = threadIdx.x;
    int gid = blockIdx.x * 256 + tid;
    se[tid] = (gid < N_EDGES) ? g_ecnt[gid] : 0;
    sn[tid] = (gid < N_NODES) ? g_ncnt[gid] : 0;
    __syncthreads();
    for (int off = 128; off > 0; off >>= 1) {
        if (tid < off) { se[tid] += se[tid + off]; sn[tid] += sn[tid + off]; }
        __syncthreads();
    }
    if (tid == 0) { g_bsum_e[blockIdx.x] = se[0]; g_bsum_n[blockIdx.x] = sn[0]; }
}

__global__ void scan2_kernel() {
    __shared__ int se[512], sn[512];
    int tid = threadIdx.x;
    int ve = (tid < NB) ? g_bsum_e[tid] : 0;
    int vn = (tid < NB) ? g_bsum_n[tid] : 0;
    se[tid] = ve; sn[tid] = vn;
    __syncthreads();
    for (int off = 1; off < 512; off <<= 1) {
        int ae = (tid >= off) ? se[tid - off] : 0;
        int an = (tid >= off) ? sn[tid - off] : 0;
        __syncthreads();
        se[tid] += ae; sn[tid] += an;
        __syncthreads();
    }
    if (tid < NB) { g_bsum_e[tid] = se[tid] - ve; g_bsum_n[tid] = sn[tid] - vn; }
    if (tid == 0) { g_estart[N_EDGES] = N_PINS; g_nstart[N_NODES] = N_PINS; }
}

__global__ void scan3_kernel() {
    __shared__ int se[256], sn[256];
    int tid = threadIdx.x;
    int gid = blockIdx.x * 256 + tid;
    int ve = (gid < N_EDGES) ? g_ecnt[gid] : 0;
    int vn = (gid < N_NODES) ? g_ncnt[gid] : 0;
    se[tid] = ve; sn[tid] = vn;
    __syncthreads();
    for (int off = 1; off < 256; off <<= 1) {
        int ae = (tid >= off) ? se[tid - off] : 0;
        int an = (tid >= off) ? sn[tid - off] : 0;
        __syncthreads();
        se[tid] += ae; sn[tid] += an;
        __syncthreads();
    }
    if (gid < N_EDGES) { g_estart[gid] = g_bsum_e[blockIdx.x] + se[tid] - ve; g_ecnt[gid] = 0; }
    if (gid < N_NODES) { g_nstart[gid] = g_bsum_n[blockIdx.x] + sn[tid] - vn; g_ncnt[gid] = 0; }
}

__global__ void fill_kernel(const int* __restrict__ nidx, const int* __restrict__ eidx) {
    int i = blockIdx.x * blockDim.x + threadIdx.x;
    if (i >= N_PINS) return;
    int n = nidx[i], e = eidx[i];
    int pe = g_estart[e] + atomicAdd(&g_ecnt[e], 1);
    g_epins[pe] = n;
    int pn = g_nstart[n] + atomicAdd(&g_ncnt[n], 1);
    g_npins[pn] = e;
}

// ---------------- gather: dst[row] = (1/deg) * sum_{p in row} src[pin_p] ----
// One warp per row; lane owns a float4 column slice; PPW pins in flight.
// SIDE 0: edge side (estart/epins, dst=g_HE). SIDE 1: node side (dst=g_G).
// SRCSEL 0: param Xp. 1: g_HE. 2: g_H.
template <int W, int SIDE, int SRCSEL>
__global__ void gather_kernel(const float* __restrict__ Xp) {
    constexpr int LPR = W / 4;     // lanes per pin-row: 8 (W=32) / 16 (W=64)
    constexpr int PPW = 32 / LPR;  // pins in parallel:   4 / 2
    int row  = (blockIdx.x * blockDim.x + threadIdx.x) >> 5;
    int lane = threadIdx.x & 31;
    if (row >= N_NODES) return;    // N_NODES == N_EDGES
    const int* start = (SIDE == 0) ? g_estart : g_nstart;
    const int* pins  = (SIDE == 0) ? g_epins  : g_npins;
    const float* src = (SRCSEL == 0) ? Xp : (SRCSEL == 1) ? g_HE : g_H;
    float* dst = (SIDE == 0) ? g_HE : g_G;
    int sub = lane / LPR;
    int c4  = (lane % LPR) << 2;
    int s = start[row], e = start[row + 1];
    float ax = 0.f, ay = 0.f, az = 0.f, aw = 0.f;
    for (int i = s + sub; i < e; i += PPW) {
        int p = pins[i];
        float4 v = *(const float4*)(src + (long)p * W + c4);
        ax += v.x; ay += v.y; az += v.z; aw += v.w;
    }
    #pragma unroll
    for (int off = LPR; off < 32; off <<= 1) {
        ax += __shfl_xor_sync(0xffffffffu, ax, off);
        ay += __shfl_xor_sync(0xffffffffu, ay, off);
        az += __shfl_xor_sync(0xffffffffu, az, off);
        aw += __shfl_xor_sync(0xffffffffu, aw, off);
    }
    if (lane < LPR) {
        float inv = (e > s) ? 1.0f / (float)(e - s) : 0.0f;
        float4 r = make_float4(ax * inv, ay * inv, az * inv, aw * inv);
        *(float4*)(dst + (long)row * W + c4) = r;
    }
}

// ---------------- layer-1 matmul + bias + layernorm + leaky -> g_H ----------
// g_G[N,32] @ W[32,64] + b -> LN(g,be) -> leaky. 32 rows/block, 256 threads,
// thread computes 2 rows x 4 cols; row stats via 16-lane shfl_xor reduce.
__global__ void matmul_ln_kernel(const float* __restrict__ W,
                                 const float* __restrict__ bias,
                                 const float* __restrict__ g,
                                 const float* __restrict__ be) {
    __shared__ __align__(16) float Ws[32 * 64];
    __shared__ float Xs[32][33];
    int tid = threadIdx.x;
    for (int i = tid; i < 32 * 64; i += 256) Ws[i] = W[i];
    int node0 = blockIdx.x * 32;
    for (int i = tid; i < 32 * 32; i += 256) {
        int r = i >> 5, c = i & 31;
        Xs[r][c] = g_G[(long)(node0 + r) * 32 + c];
    }
    __syncthreads();
    int j0 = (tid & 15) << 2;
    int r0 = (tid >> 4) << 1;
    float acc[2][4] = {};
    #pragma unroll
    for (int k = 0; k < 32; k++) {
        float x0 = Xs[r0][k], x1 = Xs[r0 + 1][k];
        float4 w = *(const float4*)&Ws[k * 64 + j0];
        acc[0][0] += x0 * w.x; acc[0][1] += x0 * w.y; acc[0][2] += x0 * w.z; acc[0][3] += x0 * w.w;
        acc[1][0] += x1 * w.x; acc[1][1] += x1 * w.y; acc[1][2] += x1 * w.z; acc[1][3] += x1 * w.w;
    }
    float b0 = bias[j0], b1 = bias[j0+1], b2 = bias[j0+2], b3 = bias[j0+3];
    float g0 = g[j0], gg1 = g[j0+1], g2 = g[j0+2], g3 = g[j0+3];
    float e0 = be[j0], e1 = be[j0+1], e2 = be[j0+2], e3 = be[j0+3];
    #pragma unroll
    for (int rr = 0; rr < 2; rr++) {
        float vx = acc[rr][0] + b0, vy = acc[rr][1] + b1;
        float vz = acc[rr][2] + b2, vw = acc[rr][3] + b3;
        float s  = vx + vy + vz + vw;
        float sq = vx*vx + vy*vy + vz*vz + vw*vw;
        #pragma unroll
        for (int off = 1; off < 16; off <<= 1) {
            s  += __shfl_xor_sync(0xffffffffu, s,  off);
            sq += __shfl_xor_sync(0xffffffffu, sq, off);
        }
        float mean = s * (1.0f / 64.0f);
        float var  = sq * (1.0f / 64.0f) - mean * mean;
        float rstd = rsqrtf(var + 1e-5f);
        float4 o;
        o.x = leaky((vx - mean) * rstd * g0 + e0);
        o.y = leaky((vy - mean) * rstd * gg1 + e1);
        o.z = leaky((vz - mean) * rstd * g2 + e2);
        o.w = leaky((vw - mean) * rstd * g3 + e3);
        *(float4*)&g_H[(long)(node0 + r0 + rr) * 64 + j0] = o;
    }
}

// ---------------- matmul: out = f(g_G[N,64] @ W[64,64] + bias) --------------
// DST 1: g_H (leaky). Generic single-output version for layer 2.
__global__ void matmul_kernel(const float* __restrict__ W,
                              const float* __restrict__ bias) {
    __shared__ __align__(16) float Ws[64 * 64];
    __shared__ float Xs[32][65];
    int tid = threadIdx.x;
    for (int i = tid; i < 64 * 64; i += 256) Ws[i] = W[i];
    int node0 = blockIdx.x * 32;
    for (int i = tid; i < 32 * 64; i += 256) {
        int r = i >> 6, c = i & 63;
        Xs[r][c] = g_G[(long)(node0 + r) * 64 + c];
    }
    __syncthreads();
    int j0 = (tid & 15) << 2;
    int r0 = (tid >> 4) << 1;
    float acc[2][4] = {};
    #pragma unroll
    for (int k = 0; k < 64; k++) {
        float x0 = Xs[r0][k], x1 = Xs[r0 + 1][k];
        float4 w = *(const float4*)&Ws[k * 64 + j0];
        acc[0][0] += x0 * w.x; acc[0][1] += x0 * w.y; acc[0][2] += x0 * w.z; acc[0][3] += x0 * w.w;
        acc[1][0] += x1 * w.x; acc[1][1] += x1 * w.y; acc[1][2] += x1 * w.z; acc[1][3] += x1 * w.w;
    }
    float b0 = bias[j0], b1 = bias[j0+1], b2 = bias[j0+2], b3 = bias[j0+3];
    #pragma unroll
    for (int rr = 0; rr < 2; rr++) {
        float4 v;
        v.x = leaky(acc[rr][0] + b0); v.y = leaky(acc[rr][1] + b1);
        v.z = leaky(acc[rr][2] + b2); v.w = leaky(acc[rr][3] + b3);
        *(float4*)&g_H[(long)(node0 + r0 + rr) * 64 + j0] = v;
    }
}

// ---------------- dual matmul: mu -> g_MU, logvar -> outp (no activation) ---
__global__ void matmul_dual_kernel(const float* __restrict__ Wa,
                                   const float* __restrict__ ba,
                                   const float* __restrict__ Wb,
                                   const float* __restrict__ bb,
                                   float* __restrict__ outp) {
    __shared__ __align__(16) float Wsa[64 * 64];
    __shared__ __align__(16) float Wsb[64 * 64];
    __shared__ float Xs[32][65];
    int tid = threadIdx.x;
    for (int i = tid; i < 64 * 64; i += 256) { Wsa[i] = Wa[i]; Wsb[i] = Wb[i]; }
    int node0 = blockIdx.x * 32;
    for (int i = tid; i < 32 * 64; i += 256) {
        int r = i >> 6, c = i & 63;
        Xs[r][c] = g_G[(long)(node0 + r) * 64 + c];
    }
    __syncthreads();
    int j0 = (tid & 15) << 2;
    int r0 = (tid >> 4) << 1;
    float accA[2][4] = {}, accB[2][4] = {};
    #pragma unroll
    for (int k = 0; k < 64; k++) {
        float x0 = Xs[r0][k], x1 = Xs[r0 + 1][k];
        float4 wa = *(const float4*)&Wsa[k * 64 + j0];
        float4 wb = *(const float4*)&Wsb[k * 64 + j0];
        accA[0][0] += x0*wa.x; accA[0][1] += x0*wa.y; accA[0][2] += x0*wa.z; accA[0][3] += x0*wa.w;
        accA[1][0] += x1*wa.x; accA[1][1] += x1*wa.y; accA[1][2] += x1*wa.z; accA[1][3] += x1*wa.w;
        accB[0][0] += x0*wb.x; accB[0][1] += x0*wb.y; accB[0][2] += x0*wb.z; accB[0][3] += x0*wb.w;
        accB[1][0] += x1*wb.x; accB[1][1] += x1*wb.y; accB[1][2] += x1*wb.z; accB[1][3] += x1*wb.w;
    }
    float a0 = ba[j0], a1 = ba[j0+1], a2 = ba[j0+2], a3 = ba[j0+3];
    float c0 = bb[j0], c1 = bb[j0+1], c2 = bb[j0+2], c3 = bb[j0+3];
    #pragma unroll
    for (int rr = 0; rr < 2; rr++) {
        long rowoff = (long)(node0 + r0 + rr) * 64 + j0;
        float4 va = make_float4(accA[rr][0]+a0, accA[rr][1]+a1, accA[rr][2]+a2, accA[rr][3]+a3);
        float4 vb = make_float4(accB[rr][0]+c0, accB[rr][1]+c1, accB[rr][2]+c2, accB[rr][3]+c3);
        *(float4*)&g_MU[rowoff] = va;
        *(float4*)&outp[rowoff] = vb;
    }
}

// ---------------- decoder: 64 -> 32 -> 8 -> 1 + sumsq -----------------------
__global__ void decode_kernel(const float* __restrict__ dW1, const float* __restrict__ db1,
                              const float* __restrict__ dW2, const float* __restrict__ db2,
                              const float* __restrict__ dW3, const float* __restrict__ db3) {
    __shared__ float W1s[64 * 32];
    __shared__ float W2s[32 * 8];
    __shared__ float W3s[8];
    __shared__ float b1s[32], b2s[8], b3s;
    __shared__ float mus[4][64];
    __shared__ float v1s[4][32];
    __shared__ float v2s[4][8];
    __shared__ float dsq[4];
    int tid = threadIdx.x;  // 128
    for (int i = tid; i < 2048; i += 128) W1s[i] = dW1[i];
    for (int i = tid; i < 256;  i += 128) W2s[i] = dW2[i];
    if (tid < 8)  W3s[tid] = dW3[tid];
    if (tid < 32) b1s[tid] = db1[tid];
    if (tid >= 32 && tid < 40) b2s[tid - 32] = db2[tid - 32];
    if (tid == 40) b3s = db3[0];
    int w = tid >> 5, lane = tid & 31;
    int node = blockIdx.x * 4 + w;
    bool active = node < N_NODES;
    if (active) {
        mus[w][lane]      = g_MU[(long)node * 64 + lane];
        mus[w][lane + 32] = g_MU[(long)node * 64 + lane + 32];
    }
    __syncthreads();
    float d = 0.f;
    if (active) {
        float a1 = b1s[lane];
        #pragma unroll
        for (int k = 0; k < 64; k++) a1 += mus[w][k] * W1s[k * 32 + lane];
        v1s[w][lane] = leaky(a1);
        __syncwarp();
        if (lane < 8) {
            float a2 = b2s[lane];
            #pragma unroll
            for (int k = 0; k < 32; k++) a2 += v1s[w][k] * W2s[k * 8 + lane];
            v2s[w][lane] = leaky(a2);
        }
        __syncwarp();
        if (lane == 0) {
            d = b3s;
            #pragma unroll
            for (int o = 0; o < 8; o++) d += v2s[w][o] * W3s[o];
            g_dvec[node] = d;
        }
    }
    if (lane == 0) dsq[w] = active ? d * d : 0.f;
    __syncthreads();
    if (tid == 0) atomicAdd(&g_sumsq, dsq[0] + dsq[1] + dsq[2] + dsq[3]);
}

__global__ void norm_write_kernel(float* __restrict__ oz, float* __restrict__ om) {
    int i = blockIdx.x * blockDim.x + threadIdx.x;
    if (i >= N_NODES) return;
    float sc = 1.0f / fmaxf(sqrtf(g_sumsq), 1e-8f);
    float v = g_dvec[i] * sc;
    oz[i] = v;
    om[i] = v;
}

// ---------------- host launch ------------------------------------------------
extern "C" void kernel_launch(void* const* d_in, const int* in_sizes, int n_in,
                              void* d_out, int out_size) {
    const float* x   = (const float*)d_in[0];
    const int*   hei = (const int*)d_in[1];   // int32 (JAX x64 disabled)
    const float *W1 = (const float*)d_in[2],  *b1  = (const float*)d_in[3];
    const float *g1 = (const float*)d_in[4],  *be1 = (const float*)d_in[5];
    const float *W2 = (const float*)d_in[6],  *b2  = (const float*)d_in[7];
    const float *Wmu= (const float*)d_in[8],  *bmu = (const float*)d_in[9];
    const float *Wlv= (const float*)d_in[10], *blv = (const float*)d_in[11];
    const float *dW1= (const float*)d_in[12], *db1 = (const float*)d_in[13];
    const float *dW2= (const float*)d_in[14], *db2 = (const float*)d_in[15];
    const float *dW3= (const float*)d_in[16], *db3 = (const float*)d_in[17];

    const int* nidx = hei;
    const int* eidx = hei + N_PINS;

    float* out    = (float*)d_out;
    float* out_z  = out;
    float* out_m  = out + N_NODES;
    float* out_lv = out + 2 * N_NODES;

    const int TB = 256;
    const int pins_blocks   = (N_PINS + TB - 1) / TB;      // 6250
    const int gather_blocks = (N_NODES * 32) / TB;         // 12500 (warp/row)
    const int mm_blocks     = N_NODES / 32;                // 3125
    const int dec_blocks    = (N_NODES + 3) / 4;
    const int n_blocks      = (N_NODES + TB - 1) / TB;

    // CSR build
    zero_cnt_kernel<<<NB, TB>>>();
    hist_kernel<<<pins_blocks, TB>>>(nidx, eidx);
    scan1_kernel<<<NB, TB>>>();
    scan2_kernel<<<1, 512>>>();
    scan3_kernel<<<NB, TB>>>();
    fill_kernel<<<pins_blocks, TB>>>(nidx, eidx);

    // layer 1: gather(x) (32-wide) -> @W1+b1 -> LN -> leaky -> g_H
    gather_kernel<32, 0, 0><<<gather_blocks, TB>>>(x);
    gather_kernel<32, 1, 1><<<gather_blocks, TB>>>(nullptr);
    matmul_ln_kernel<<<mm_blocks, TB>>>(W1, b1, g1, be1);

    // layer 2: gather(g_H) -> @W2+b2 -> leaky -> g_H
    gather_kernel<64, 0, 2><<<gather_blocks, TB>>>(nullptr);
    gather_kernel<64, 1, 1><<<gather_blocks, TB>>>(nullptr);
    matmul_kernel<<<mm_blocks, TB>>>(W2, b2);

    // mu / logvar share one gathered tensor
    gather_kernel<64, 0, 2><<<gather_blocks, TB>>>(nullptr);
    gather_kernel<64, 1, 1><<<gather_blocks, TB>>>(nullptr);
    matmul_dual_kernel<<<mm_blocks, TB>>>(Wmu, bmu, Wlv, blv, out_lv);

    // decode(z = mu) once; z_orth == mu_orth in eval mode
    decode_kernel<<<dec_blocks, 128>>>(dW1, db1, dW2, db2, dW3, db3);
    norm_write_kernel<<<n_blocks, TB>>>(out_z, out_m);
}